// round 12
// baseline (speedup 1.0000x reference)
#include <cuda_runtime.h>
#include <cuda_bf16.h>
#include <stdint.h>

#define B_ 4
#define T_ 1024
#define NX_ 1024
#define H_ 16
#define D_ 64
#define KMAX_ 32
#define NLOC_ 64

__device__ __nv_bfloat16 g_xs[2][B_*T_*NX_];
__device__ __nv_bfloat16 g_w1s[2][NX_*3*NX_];
__device__ __nv_bfloat16 g_w2s[2][NX_*NX_];
__device__ __nv_bfloat16 g_atts[2][B_*T_*NX_];
__device__ float g_qkv[B_*T_*3*NX_];
__device__ float g_lr2[B_*H_*NLOC_*T_];

// ---------------- FMA-pipe exp (no MUFU) ----------------
__device__ __forceinline__ float fast_exp(float x) {
    x = fmaxf(x, -80.0f);
    float t = x * 1.44269504088896341f;
    float z = t + 12582912.0f;
    int   ki = __float_as_int(z) - 0x4B400000;
    float f = t - (z - 12582912.0f);
    float p = 0.00133335581f;
    p = fmaf(p, f, 0.00961812910f);
    p = fmaf(p, f, 0.05550410866f);
    p = fmaf(p, f, 0.24022650696f);
    p = fmaf(p, f, 0.69314718056f);
    p = fmaf(p, f, 1.0f);
    return __int_as_float(__float_as_int(p) + (ki << 23));
}

// ---------------- split: fp32 -> (hi, lo) bf16 planes ----------------
__global__ __launch_bounds__(256) void split_kernel(
    const float* __restrict__ in, __nv_bfloat16* __restrict__ hi,
    __nv_bfloat16* __restrict__ lo, int n4)
{
    int i = blockIdx.x * 256 + threadIdx.x;
    if (i >= n4) return;
    float4 v = *(const float4*)(in + i * 4);
    __nv_bfloat162 hh0, hh1, ll0, ll1;
    hh0.x = __float2bfloat16(v.x); hh0.y = __float2bfloat16(v.y);
    hh1.x = __float2bfloat16(v.z); hh1.y = __float2bfloat16(v.w);
    ll0.x = __float2bfloat16(v.x - __bfloat162float(hh0.x));
    ll0.y = __float2bfloat16(v.y - __bfloat162float(hh0.y));
    ll1.x = __float2bfloat16(v.z - __bfloat162float(hh1.x));
    ll1.y = __float2bfloat16(v.w - __bfloat162float(hh1.y));
    *(uint2*)(hi + i * 4) = make_uint2(*(uint32_t*)&hh0, *(uint32_t*)&hh1);
    *(uint2*)(lo + i * 4) = make_uint2(*(uint32_t*)&ll0, *(uint32_t*)&ll1);
}

__device__ __forceinline__ void packsplit(float x, float y, uint32_t& hi, uint32_t& lo) {
    __nv_bfloat162 h, l;
    h.x = __float2bfloat16(x); h.y = __float2bfloat16(y);
    l.x = __float2bfloat16(x - __bfloat162float(h.x));
    l.y = __float2bfloat16(y - __bfloat162float(h.y));
    hi = *(uint32_t*)&h; lo = *(uint32_t*)&l;
}

#define MMA_BF16(D, A0,A1,A2,A3, B0,B1) \
    asm volatile("mma.sync.aligned.m16n8k16.row.col.f32.bf16.bf16.f32 " \
        "{%0,%1,%2,%3},{%4,%5,%6,%7},{%8,%9},{%0,%1,%2,%3};" \
        : "+f"(D[0]), "+f"(D[1]), "+f"(D[2]), "+f"(D[3]) \
        : "r"(A0), "r"(A1), "r"(A2), "r"(A3), "r"(B0), "r"(B1))

#define LDSM_X4(R, ADDR) \
    asm volatile("ldmatrix.sync.aligned.m8n8.x4.shared.b16 {%0,%1,%2,%3}, [%4];" \
        : "=r"(R[0]), "=r"(R[1]), "=r"(R[2]), "=r"(R[3]) : "r"(ADDR))
#define LDSM_X4T(R, ADDR) \
    asm volatile("ldmatrix.sync.aligned.m8n8.x4.trans.shared.b16 {%0,%1,%2,%3}, [%4];" \
        : "=r"(R[0]), "=r"(R[1]), "=r"(R[2]), "=r"(R[3]) : "r"(ADDR))

#define CP_ASYNC16(DST, SRC) \
    asm volatile("cp.async.cg.shared.global [%0], [%1], 16;" :: "r"(DST), "l"(SRC))
#define CP_COMMIT() asm volatile("cp.async.commit_group;")
#define CP_WAIT2()  asm volatile("cp.async.wait_group 2;")

// ---------------- dense bf16x3 GEMM, cp.async 4-stage pipeline ----------------
// smem (dynamic): As[4][128][40] bf16 then Bs[4][32][136] bf16 = 75776 bytes.
#define GEMM_SMEM (4*128*40*2 + 4*32*136*2)

__global__ __launch_bounds__(256) void gemm_bf16x3p(
    const __nv_bfloat16* __restrict__ A, const __nv_bfloat16* __restrict__ W,
    const float* __restrict__ bias, float* __restrict__ out, int N)
{
    extern __shared__ __nv_bfloat16 gsm[];
    __nv_bfloat16 (*As)[128][40] = (__nv_bfloat16(*)[128][40])gsm;
    __nv_bfloat16 (*Bs)[32][136] = (__nv_bfloat16(*)[32][136])(gsm + 4 * 128 * 40);

    const int n0 = blockIdx.x * 128;
    const int m0 = blockIdx.y * 128;
    const int tid = threadIdx.x;
    const int lane = tid & 31, w = tid >> 5;
    const int wm = (w >> 1) * 32, wn = (w & 1) * 64;
    const size_t ASTRIDE = (size_t)4096 * 1024;
    const size_t WSTRIDE = (size_t)1024 * N;

    float acc[2][8][4];
    #pragma unroll
    for (int mt = 0; mt < 2; mt++)
        #pragma unroll
        for (int nt = 0; nt < 8; nt++)
            #pragma unroll
            for (int i = 0; i < 4; i++) acc[mt][nt][i] = 0.0f;

    // cp.async assignments: 512 16B-chunks per tile, 2 per thread.
    auto issue = [&](int i, int st) {
        int r = i >> 5, sk = (i & 31) * 32;
        const __nv_bfloat16* Ap = A + (r == 2 ? ASTRIDE : 0);
        const __nv_bfloat16* Wp = W + (r == 1 ? WSTRIDE : 0);
        #pragma unroll
        for (int cc = 0; cc < 2; cc++) {
            int c = tid + cc * 256;
            int arow = c >> 2, akc = (c & 3) * 8;
            uint32_t da = (uint32_t)__cvta_generic_to_shared(&As[st][arow][akc]);
            CP_ASYNC16(da, Ap + (size_t)(m0 + arow) * 1024 + sk + akc);
            int brow = c >> 4, bnc = (c & 15) * 8;
            uint32_t db = (uint32_t)__cvta_generic_to_shared(&Bs[st][brow][bnc]);
            CP_ASYNC16(db, Wp + (size_t)(sk + brow) * N + n0 + bnc);
        }
        CP_COMMIT();
    };

    issue(0, 0); issue(1, 1); issue(2, 2);

    for (int i = 0; i < 96; i++) {
        CP_WAIT2();
        __syncthreads();
        const int st = i & 3;
        #pragma unroll
        for (int ks = 0; ks < 2; ks++) {
            const int k0 = ks * 16;
            uint32_t a[2][4], bb[4][4];
            #pragma unroll
            for (int mt = 0; mt < 2; mt++) {
                uint32_t sa = (uint32_t)__cvta_generic_to_shared(
                    &As[st][wm + mt * 16 + (lane & 15)][k0 + (lane >> 4) * 8]);
                LDSM_X4(a[mt], sa);
            }
            #pragma unroll
            for (int np = 0; np < 4; np++) {
                uint32_t sb = (uint32_t)__cvta_generic_to_shared(
                    &Bs[st][k0 + (lane & 15)][wn + np * 16 + (lane >> 4) * 8]);
                LDSM_X4T(bb[np], sb);
            }
            #pragma unroll
            for (int mt = 0; mt < 2; mt++)
                #pragma unroll
                for (int nt = 0; nt < 8; nt++)
                    MMA_BF16(acc[mt][nt], a[mt][0], a[mt][1], a[mt][2], a[mt][3],
                             bb[nt >> 1][(nt & 1) * 2], bb[nt >> 1][(nt & 1) * 2 + 1]);
        }
        if (i + 3 < 96) issue(i + 3, (i + 3) & 3);
        else CP_COMMIT();   // keep group-count invariant for wait_group 2
    }

    #pragma unroll
    for (int mt = 0; mt < 2; mt++) {
        #pragma unroll
        for (int nt = 0; nt < 8; nt++) {
            int row = m0 + wm + mt * 16 + (lane >> 2);
            int col = n0 + wn + nt * 8 + (lane & 3) * 2;
            float b0 = bias[col], b1 = bias[col + 1];
            float2 o0 = make_float2(acc[mt][nt][0] + b0, acc[mt][nt][1] + b1);
            float2 o1 = make_float2(acc[mt][nt][2] + b0, acc[mt][nt][3] + b1);
            *(float2*)(out + (size_t)row * N + col) = o0;
            *(float2*)(out + (size_t)(row + 8) * N + col) = o1;
        }
    }
}

// ---------------- lr2 ----------------
__global__ __launch_bounds__(256) void lr2_kernel(const float* __restrict__ LR_Q)
{
    __shared__ float LQ[64][64];
    __shared__ float Ks[64][65];
    const int bh = blockIdx.y;
    const int b = bh >> 4, h = bh & (H_ - 1);
    const int s0 = blockIdx.x * 64;
    const int tid = threadIdx.x;

    for (int it = 0; it < 16; it++) {
        int f = it * 256 + tid;
        LQ[f >> 6][f & 63] = LR_Q[(size_t)(h * 64 + (f >> 6)) * 64 + (f & 63)];
    }
    for (int it = 0; it < 16; it++) {
        int f = it * 256 + tid;
        Ks[f >> 6][f & 63] =
            g_qkv[(size_t)(b * T_ + s0 + (f >> 6)) * 3072 + 1024 + h * 64 + (f & 63)];
    }
    __syncthreads();

    const int s = tid & 63;
    const int g = tid >> 6;
    float acc[16];
    #pragma unroll
    for (int nn = 0; nn < 16; nn++) acc[nn] = 0.0f;
    for (int d = 0; d < 64; d++) {
        float kv = Ks[s][d];
        #pragma unroll
        for (int nn = 0; nn < 16; nn++) acc[nn] += LQ[g * 16 + nn][d] * kv;
    }
    #pragma unroll
    for (int nn = 0; nn < 16; nn++)
        g_lr2[(size_t)(bh * 64 + g * 16 + nn) * T_ + s0 + s] = acc[nn] * 0.125f;
}

// ---------------- fused attention: MMA, 2 CTAs/SM (unchanged from R11) ----------------
#define ATT_SMEM 112272

__global__ void __launch_bounds__(256, 2) attn_kernel(
    const int* __restrict__ rel, const float* __restrict__ tds,
    const float* __restrict__ LR_K, const int* __restrict__ LR_map,
    const float* __restrict__ rel_w_emb, const float* __restrict__ rel_k_emb,
    const float* __restrict__ rel_v_emb)
{
    extern __shared__ char smraw[];
    __nv_bfloat16* kh  = (__nv_bfloat16*)(smraw);
    __nv_bfloat16* kl  = kh + 64 * 72;
    __nv_bfloat16* vh  = kl + 64 * 72;
    __nv_bfloat16* vl  = vh + 64 * 72;
    __nv_bfloat16* qhp = (__nv_bfloat16*)(smraw);
    float*         lr2s = (float*)(smraw + 36864);
    __nv_bfloat16* pstg = (__nv_bfloat16*)(smraw + 54272);
    __nv_bfloat16* lr1  = (__nv_bfloat16*)(smraw + 71168);
    float*         qf   = (float*)(smraw + 54272);
    float*         qr   = (float*)(smraw + 88064);
    __nv_bfloat16* rvD  = (__nv_bfloat16*)(smraw + 107008);
    float*         rv0  = (float*)(smraw + 111760);
    float*         relw = (float*)(smraw + 112016);

    const int bid = blockIdx.x;
    const int rb = 7 - (bid >> 6);
    const int bh = bid & 63;
    const int t0 = rb * 128;
    const int b = bh >> 4, h = bh & 15;
    const int tid = threadIdx.x;
    const int lane = tid & 31, w = tid >> 5;
    const int r8 = lane >> 2, cp = lane & 3;
    const int tw = t0 + w * 16;
    const int lra = w * 16 + r8;
    const int ta = t0 + lra, tb2 = ta + 8;

    const float* qbase = g_qkv + (size_t)b * T_ * 3072 + h * 64;
    const float* kbase = qbase + 1024;
    const float* vbase = qbase + 2048;
    const float* lr2base = g_lr2 + (size_t)bh * NLOC_ * T_;
    const int* relbase = rel + (size_t)b * T_ * T_;
    const int* lmbase = LR_map + (size_t)b * T_ * T_;
    const float* tdsbase = tds + (size_t)bh * T_ * T_;

    for (int f = tid; f < 2048; f += 256) {
        int row = f >> 4, dq = (f & 15) * 4;
        float4 qv = *(const float4*)(qbase + (size_t)(t0 + row) * 3072 + dq);
        qf[row * 65 + dq + 0] = qv.x; qf[row * 65 + dq + 1] = qv.y;
        qf[row * 65 + dq + 2] = qv.z; qf[row * 65 + dq + 3] = qv.w;
    }
    if (tid < 64) { relw[tid] = rel_w_emb[tid * H_ + h]; rv0[tid] = rel_v_emb[tid]; }
    for (int f = tid; f < 33 * 64; f += 256) {
        int id = f >> 6, d = f & 63;
        rvD[id * 72 + d] = __float2bfloat16(rel_v_emb[id * 64 + d] - rel_v_emb[d]);
    }
    __syncthreads();

    for (int task = tid; task < 33 * 128; task += 256) {
        int id = task >> 7, lr = task & 127;
        const float* rk = rel_k_emb + id * 64;
        float a = 0.0f;
        #pragma unroll 8
        for (int d = 0; d < 64; d++) a += qf[lr * 65 + d] * rk[d];
        qr[lr * 37 + id] = a;
    }
    float lr1v[32];
    #pragma unroll
    for (int kk = 0; kk < 32; kk++) {
        int task = tid + kk * 256;
        int n = task >> 7, lr = task & 127;
        const float* lk = LR_K + (size_t)(h * 64 + n) * 64;
        float a = 0.0f;
        #pragma unroll 8
        for (int d = 0; d < 64; d++) a += qf[lr * 65 + d] * lk[d];
        lr1v[kk] = a * 0.125f;
    }
    for (int f = tid; f < 2048; f += 256) {
        int row = f >> 4, dq = (f & 15) * 4;
        __nv_bfloat162 h0, h1;
        h0.x = __float2bfloat16(qf[row * 65 + dq + 0]);
        h0.y = __float2bfloat16(qf[row * 65 + dq + 1]);
        h1.x = __float2bfloat16(qf[row * 65 + dq + 2]);
        h1.y = __float2bfloat16(qf[row * 65 + dq + 3]);
        *(uint32_t*)&qhp[row * 72 + dq]     = *(uint32_t*)&h0;
        *(uint32_t*)&qhp[row * 72 + dq + 2] = *(uint32_t*)&h1;
    }
    __syncthreads();
    #pragma unroll
    for (int kk = 0; kk < 32; kk++) {
        int task = tid + kk * 256;
        int n = task >> 7, lr = task & 127;
        lr1[lr * 66 + n] = __float2bfloat16(lr1v[kk]);
    }
    const int arow = w * 16 + (lane & 15);
    const int acol8 = (lane >> 4) * 8;
    uint32_t qfh[4][4];
    #pragma unroll
    for (int ks = 0; ks < 4; ks++) {
        uint32_t sa = (uint32_t)__cvta_generic_to_shared(
            &qhp[arow * 72 + ks * 16 + acol8]);
        LDSM_X4(qfh[ks], sa);
    }
    __syncthreads();

    const float qr0a = qr[lra * 37], qr0b = qr[(lra + 8) * 37];
    float m0 = -1e30f, m1 = -1e30f, l0_ = 0.0f, l1_ = 0.0f;
    float oacc[8][4];
    #pragma unroll
    for (int nt = 0; nt < 8; nt++)
        #pragma unroll
        for (int i = 0; i < 4; i++) oacc[nt][i] = 0.0f;

    const int nchunk = 2 * rb + 2;
    const int fs = tid >> 4, fdq = (tid & 15) * 4;

    for (int c = 0; c < nchunk; c++) {
        const int s0c = c * 64;
        __syncthreads();
        #pragma unroll
        for (int i = 0; i < 4; i++) {
            int s = fs + i * 16;
            float4 kv = *(const float4*)(kbase + (size_t)(s0c + s) * 3072 + fdq);
            float4 vv = *(const float4*)(vbase + (size_t)(s0c + s) * 3072 + fdq);
            float4 l2 = *(const float4*)(lr2base + (size_t)s * T_ + s0c + fdq);
            float ka[4] = {kv.x, kv.y, kv.z, kv.w};
            #pragma unroll
            for (int j = 0; j < 4; j++) {
                __nv_bfloat16 hh = __float2bfloat16(ka[j]);
                kh[(fdq + j) * 72 + s] = hh;
                kl[(fdq + j) * 72 + s] = __float2bfloat16(ka[j] - __bfloat162float(hh));
            }
            uint32_t vh0, vl0, vh1, vl1;
            packsplit(vv.x, vv.y, vh0, vl0);
            packsplit(vv.z, vv.w, vh1, vl1);
            *(uint32_t*)&vh[s * 72 + fdq]     = vh0;
            *(uint32_t*)&vh[s * 72 + fdq + 2] = vh1;
            *(uint32_t*)&vl[s * 72 + fdq]     = vl0;
            *(uint32_t*)&vl[s * 72 + fdq + 2] = vl1;
            *(float4*)&lr2s[s * 68 + fdq] = l2;
        }
        __syncthreads();

        if (s0c > tw + 15) continue;
        const bool far = (s0c + 96 <= tw);

        float sfr[8][4];
        #pragma unroll
        for (int nt = 0; nt < 8; nt++)
            #pragma unroll
            for (int i = 0; i < 4; i++) sfr[nt][i] = 0.0f;

        #pragma unroll
        for (int ks = 0; ks < 4; ks++) {
            const int k0 = ks * 16;
            #pragma unroll
            for (int ng = 0; ng < 4; ng++) {
                uint32_t bh_[4], bl_[4];
                uint32_t sb1 = (uint32_t)__cvta_generic_to_shared(
                    &kh[(k0 + (lane & 15)) * 72 + ng * 16 + acol8]);
                LDSM_X4T(bh_, sb1);
                uint32_t sb2 = (uint32_t)__cvta_generic_to_shared(
                    &kl[(k0 + (lane & 15)) * 72 + ng * 16 + acol8]);
                LDSM_X4T(bl_, sb2);
                const int nt0 = ng * 2;
                MMA_BF16(sfr[nt0],     qfh[ks][0], qfh[ks][1], qfh[ks][2], qfh[ks][3], bh_[0], bh_[1]);
                MMA_BF16(sfr[nt0 + 1], qfh[ks][0], qfh[ks][1], qfh[ks][2], qfh[ks][3], bh_[2], bh_[3]);
                MMA_BF16(sfr[nt0],     qfh[ks][0], qfh[ks][1], qfh[ks][2], qfh[ks][3], bl_[0], bl_[1]);
                MMA_BF16(sfr[nt0 + 1], qfh[ks][0], qfh[ks][1], qfh[ks][2], qfh[ks][3], bl_[2], bl_[3]);
            }
        }

        #pragma unroll
        for (int nt = 0; nt < 8; nt++) {
            const int sl0 = nt * 8 + cp * 2;
            const int sb_ = s0c + sl0;
            const size_t offA = (size_t)ta * T_ + sb_;
            const size_t offB = (size_t)tb2 * T_ + sb_;
            int2 rA = *(const int2*)(relbase + offA);
            int2 rB = *(const int2*)(relbase + offB);
            int2 lA = *(const int2*)(lmbase + offA);
            int2 lB = *(const int2*)(lmbase + offB);
            float2 tA = *(const float2*)(tdsbase + offA);
            float2 tB = *(const float2*)(tdsbase + offB);
            float qa0, qa1, qb0, qb1;
            if (far) { qa0 = qa1 = qr0a; qb0 = qb1 = qr0b; }
            else {
                int i0 = min(32, max(0, sb_ - ta + 32));
                int i1 = min(32, max(0, sb_ + 1 - ta + 32));
                int i2 = min(32, max(0, sb_ - tb2 + 32));
                int i3 = min(32, max(0, sb_ + 1 - tb2 + 32));
                qa0 = qr[lra * 37 + i0]; qa1 = qr[lra * 37 + i1];
                qb0 = qr[(lra + 8) * 37 + i2]; qb1 = qr[(lra + 8) * 37 + i3];
            }
            float x0 = fmaf((sfr[nt][0] + qa0) * 0.125f, relw[rA.x], tA.x)
                       + __bfloat162float(lr1[lra * 66 + lA.x]) + lr2s[lA.x * 68 + sl0];
            float x1 = fmaf((sfr[nt][1] + qa1) * 0.125f, relw[rA.y], tA.y)
                       + __bfloat162float(lr1[lra * 66 + lA.y]) + lr2s[lA.y * 68 + sl0 + 1];
            float x2 = fmaf((sfr[nt][2] + qb0) * 0.125f, relw[rB.x], tB.x)
                       + __bfloat162float(lr1[(lra + 8) * 66 + lB.x]) + lr2s[lB.x * 68 + sl0];
            float x3 = fmaf((sfr[nt][3] + qb1) * 0.125f, relw[rB.y], tB.y)
                       + __bfloat162float(lr1[(lra + 8) * 66 + lB.y]) + lr2s[lB.y * 68 + sl0 + 1];
            sfr[nt][0] = (sb_     > ta ) ? -1e30f : x0 * 0.70710678118f;
            sfr[nt][1] = (sb_ + 1 > ta ) ? -1e30f : x1 * 0.70710678118f;
            sfr[nt][2] = (sb_     > tb2) ? -1e30f : x2 * 0.70710678118f;
            sfr[nt][3] = (sb_ + 1 > tb2) ? -1e30f : x3 * 0.70710678118f;
        }

        float mxa = -1e30f, mxb = -1e30f;
        #pragma unroll
        for (int nt = 0; nt < 8; nt++) {
            mxa = fmaxf(mxa, fmaxf(sfr[nt][0], sfr[nt][1]));
            mxb = fmaxf(mxb, fmaxf(sfr[nt][2], sfr[nt][3]));
        }
        mxa = fmaxf(mxa, __shfl_xor_sync(0xffffffffu, mxa, 1));
        mxa = fmaxf(mxa, __shfl_xor_sync(0xffffffffu, mxa, 2));
        mxb = fmaxf(mxb, __shfl_xor_sync(0xffffffffu, mxb, 1));
        mxb = fmaxf(mxb, __shfl_xor_sync(0xffffffffu, mxb, 2));
        float mna = fmaxf(m0, mxa), sc0 = fast_exp(m0 - mna);
        float mnb = fmaxf(m1, mxb), sc1 = fast_exp(m1 - mnb);
        float pa = 0.0f, pb = 0.0f;
        #pragma unroll
        for (int nt = 0; nt < 8; nt++) {
            sfr[nt][0] = fast_exp(sfr[nt][0] - mna);
            sfr[nt][1] = fast_exp(sfr[nt][1] - mna);
            sfr[nt][2] = fast_exp(sfr[nt][2] - mnb);
            sfr[nt][3] = fast_exp(sfr[nt][3] - mnb);
            pa += sfr[nt][0] + sfr[nt][1];
            pb += sfr[nt][2] + sfr[nt][3];
        }
        pa += __shfl_xor_sync(0xffffffffu, pa, 1);
        pa += __shfl_xor_sync(0xffffffffu, pa, 2);
        pb += __shfl_xor_sync(0xffffffffu, pb, 1);
        pb += __shfl_xor_sync(0xffffffffu, pb, 2);
        l0_ = l0_ * sc0 + pa; m0 = mna;
        l1_ = l1_ * sc1 + pb; m1 = mnb;
        #pragma unroll
        for (int nt = 0; nt < 8; nt++) {
            oacc[nt][0] *= sc0; oacc[nt][1] *= sc0;
            oacc[nt][2] *= sc1; oacc[nt][3] *= sc1;
        }

        if (!far) {
            #pragma unroll
            for (int nt = 0; nt < 8; nt++) {
                int sl0 = nt * 8 + cp * 2;
                pstg[lra * 66 + sl0]           = __float2bfloat16(sfr[nt][0]);
                pstg[lra * 66 + sl0 + 1]       = __float2bfloat16(sfr[nt][1]);
                pstg[(lra + 8) * 66 + sl0]     = __float2bfloat16(sfr[nt][2]);
                pstg[(lra + 8) * 66 + sl0 + 1] = __float2bfloat16(sfr[nt][3]);
            }
        }

        uint32_t ph[4][4], pl2[4][4];
        #pragma unroll
        for (int kk = 0; kk < 4; kk++) {
            packsplit(sfr[2*kk][0],   sfr[2*kk][1],   ph[kk][0], pl2[kk][0]);
            packsplit(sfr[2*kk][2],   sfr[2*kk][3],   ph[kk][1], pl2[kk][1]);
            packsplit(sfr[2*kk+1][0], sfr[2*kk+1][1], ph[kk][2], pl2[kk][2]);
            packsplit(sfr[2*kk+1][2], sfr[2*kk+1][3], ph[kk][3], pl2[kk][3]);
        }

        #pragma unroll
        for (int kk = 0; kk < 4; kk++) {
            const int k0 = kk * 16;
            #pragma unroll
            for (int ng = 0; ng < 4; ng++) {
                uint32_t bb[4];
                uint32_t sb = (uint32_t)__cvta_generic_to_shared(
                    &vh[(k0 + (lane & 15)) * 72 + ng * 16 + acol8]);
                LDSM_X4T(bb, sb);
                const int nt0 = ng * 2;
                MMA_BF16(oacc[nt0],     ph[kk][0], ph[kk][1], ph[kk][2], ph[kk][3], bb[0], bb[1]);
                MMA_BF16(oacc[nt0 + 1], ph[kk][0], ph[kk][1], ph[kk][2], ph[kk][3], bb[2], bb[3]);
                MMA_BF16(oacc[nt0],     pl2[kk][0], pl2[kk][1], pl2[kk][2], pl2[kk][3], bb[0], bb[1]);
                MMA_BF16(oacc[nt0 + 1], pl2[kk][0], pl2[kk][1], pl2[kk][2], pl2[kk][3], bb[2], bb[3]);
            }
        }
        #pragma unroll
        for (int kk = 0; kk < 4; kk++) {
            const int k0 = kk * 16;
            #pragma unroll
            for (int ng = 0; ng < 4; ng++) {
                uint32_t bb[4];
                uint32_t sb = (uint32_t)__cvta_generic_to_shared(
                    &vl[(k0 + (lane & 15)) * 72 + ng * 16 + acol8]);
                LDSM_X4T(bb, sb);
                const int nt0 = ng * 2;
                MMA_BF16(oacc[nt0],     ph[kk][0], ph[kk][1], ph[kk][2], ph[kk][3], bb[0], bb[1]);
                MMA_BF16(oacc[nt0 + 1], ph[kk][0], ph[kk][1], ph[kk][2], ph[kk][3], bb[2], bb[3]);
            }
        }

        if (!far) {
            __syncwarp();
            #pragma unroll
            for (int rsel = 0; rsel < 2; rsel++) {
                const int t = rsel ? tb2 : ta;
                const __nv_bfloat16* Prow = pstg + (size_t)(lra + rsel * 8) * 66;
                for (int j = 0; j <= 32; j++) {
                    int sl = t - 32 + j - s0c;
                    if (sl < 0 || sl > 63) continue;
                    float p = __bfloat162float(Prow[sl]);
                    #pragma unroll
                    for (int nt = 0; nt < 8; nt++) {
                        uint32_t rvu = *(const uint32_t*)&rvD[j * 72 + nt * 8 + cp * 2];
                        __nv_bfloat162 rv2 = *(__nv_bfloat162*)&rvu;
                        oacc[nt][rsel * 2 + 0] += p * __bfloat162float(rv2.x);
                        oacc[nt][rsel * 2 + 1] += p * __bfloat162float(rv2.y);
                    }
                }
            }
        }
    }

    const float invl0 = 1.0f / l0_, invl1 = 1.0f / l1_;
    #pragma unroll
    for (int rsel = 0; rsel < 2; rsel++) {
        const int t = rsel ? tb2 : ta;
        const float invl = rsel ? invl1 : invl0;
        #pragma unroll
        for (int nt = 0; nt < 8; nt++) {
            int c0 = nt * 8 + cp * 2;
            float o0 = oacc[nt][rsel * 2 + 0] * invl + rv0[c0];
            float o1 = oacc[nt][rsel * 2 + 1] * invl + rv0[c0 + 1];
            uint32_t hp, lp;
            packsplit(o0, o1, hp, lp);
            size_t oidx = (size_t)(b * T_ + t) * NX_ + h * 64 + c0;
            *(uint32_t*)&g_atts[0][oidx] = hp;
            *(uint32_t*)&g_atts[1][oidx] = lp;
        }
    }
}

// ---------------- launch ----------------
extern "C" void kernel_launch(void* const* d_in, const int* in_sizes, int n_in,
                              void* d_out, int out_size)
{
    const float* x          = (const float*)d_in[0];
    const int*   rel        = (const int*)  d_in[1];
    const float* tds        = (const float*)d_in[2];
    const float* LR_Q       = (const float*)d_in[3];
    const float* LR_K       = (const float*)d_in[4];
    const int*   LR_map     = (const int*)  d_in[5];
    const float* c_attn_w   = (const float*)d_in[6];
    const float* c_attn_b   = (const float*)d_in[7];
    const float* c_proj_w   = (const float*)d_in[8];
    const float* c_proj_b   = (const float*)d_in[9];
    const float* rel_w_emb  = (const float*)d_in[10];
    const float* rel_k_emb  = (const float*)d_in[11];
    const float* rel_v_emb  = (const float*)d_in[12];
    float* out = (float*)d_out;

    cudaFuncSetAttribute(attn_kernel, cudaFuncAttributeMaxDynamicSharedMemorySize,
                         ATT_SMEM);
    cudaFuncSetAttribute(gemm_bf16x3p, cudaFuncAttributeMaxDynamicSharedMemorySize,
                         GEMM_SMEM);

    __nv_bfloat16 *xs, *w1s, *w2s, *atts;
    cudaGetSymbolAddress((void**)&xs, g_xs);
    cudaGetSymbolAddress((void**)&w1s, g_w1s);
    cudaGetSymbolAddress((void**)&w2s, g_w2s);
    cudaGetSymbolAddress((void**)&atts, g_atts);
    float* qkv_buf; cudaGetSymbolAddress((void**)&qkv_buf, g_qkv);

    const int NXM = B_ * T_ * NX_;
    split_kernel<<<NXM / 1024, 256>>>(x, xs, xs + NXM, NXM / 4);
    split_kernel<<<(NX_*3*NX_) / 1024, 256>>>(c_attn_w, w1s, w1s + NX_*3*NX_, (NX_*3*NX_) / 4);
    split_kernel<<<(NX_*NX_) / 1024, 256>>>(c_proj_w, w2s, w2s + NX_*NX_, (NX_*NX_) / 4);

    gemm_bf16x3p<<<dim3(24, 32), 256, GEMM_SMEM>>>(xs, w1s, c_attn_b, qkv_buf, 3072);
    lr2_kernel<<<dim3(16, 64), 256>>>(LR_Q);
    attn_kernel<<<512, 256, ATT_SMEM>>>(
        rel, tds, LR_K, LR_map, rel_w_emb, rel_k_emb, rel_v_emb);
    gemm_bf16x3p<<<dim3(8, 32), 256, GEMM_SMEM>>>(atts, w2s, c_proj_b, out, 1024);
}

// round 13
// speedup vs baseline: 1.0067x; 1.0067x over previous
#include <cuda_runtime.h>
#include <cuda_bf16.h>
#include <stdint.h>

#define B_ 4
#define T_ 1024
#define NX_ 1024
#define H_ 16
#define D_ 64
#define KMAX_ 32
#define NLOC_ 64

__device__ __nv_bfloat16 g_xs[2][B_*T_*NX_];
__device__ __nv_bfloat16 g_w1s[2][NX_*3*NX_];
__device__ __nv_bfloat16 g_w2s[2][NX_*NX_];
__device__ __nv_bfloat16 g_atts[2][B_*T_*NX_];
__device__ float g_qkv[B_*T_*3*NX_];
__device__ float g_lr2[B_*H_*NLOC_*T_];

// ---------------- FMA-pipe exp (no MUFU) ----------------
__device__ __forceinline__ float fast_exp(float x) {
    x = fmaxf(x, -80.0f);
    float t = x * 1.44269504088896341f;
    float z = t + 12582912.0f;
    int   ki = __float_as_int(z) - 0x4B400000;
    float f = t - (z - 12582912.0f);
    float p = 0.00133335581f;
    p = fmaf(p, f, 0.00961812910f);
    p = fmaf(p, f, 0.05550410866f);
    p = fmaf(p, f, 0.24022650696f);
    p = fmaf(p, f, 0.69314718056f);
    p = fmaf(p, f, 1.0f);
    return __int_as_float(__float_as_int(p) + (ki << 23));
}

// ---------------- split: fp32 -> (hi, lo) bf16 planes ----------------
__global__ __launch_bounds__(256) void split_kernel(
    const float* __restrict__ in, __nv_bfloat16* __restrict__ hi,
    __nv_bfloat16* __restrict__ lo, int n4)
{
    int i = blockIdx.x * 256 + threadIdx.x;
    if (i >= n4) return;
    float4 v = *(const float4*)(in + i * 4);
    __nv_bfloat162 hh0, hh1, ll0, ll1;
    hh0.x = __float2bfloat16(v.x); hh0.y = __float2bfloat16(v.y);
    hh1.x = __float2bfloat16(v.z); hh1.y = __float2bfloat16(v.w);
    ll0.x = __float2bfloat16(v.x - __bfloat162float(hh0.x));
    ll0.y = __float2bfloat16(v.y - __bfloat162float(hh0.y));
    ll1.x = __float2bfloat16(v.z - __bfloat162float(hh1.x));
    ll1.y = __float2bfloat16(v.w - __bfloat162float(hh1.y));
    *(uint2*)(hi + i * 4) = make_uint2(*(uint32_t*)&hh0, *(uint32_t*)&hh1);
    *(uint2*)(lo + i * 4) = make_uint2(*(uint32_t*)&ll0, *(uint32_t*)&ll1);
}

__device__ __forceinline__ void packsplit(float x, float y, uint32_t& hi, uint32_t& lo) {
    __nv_bfloat162 h, l;
    h.x = __float2bfloat16(x); h.y = __float2bfloat16(y);
    l.x = __float2bfloat16(x - __bfloat162float(h.x));
    l.y = __float2bfloat16(y - __bfloat162float(h.y));
    hi = *(uint32_t*)&h; lo = *(uint32_t*)&l;
}

#define MMA_BF16(D, A0,A1,A2,A3, B0,B1) \
    asm volatile("mma.sync.aligned.m16n8k16.row.col.f32.bf16.bf16.f32 " \
        "{%0,%1,%2,%3},{%4,%5,%6,%7},{%8,%9},{%0,%1,%2,%3};" \
        : "+f"(D[0]), "+f"(D[1]), "+f"(D[2]), "+f"(D[3]) \
        : "r"(A0), "r"(A1), "r"(A2), "r"(A3), "r"(B0), "r"(B1))

#define LDSM_X4(R, ADDR) \
    asm volatile("ldmatrix.sync.aligned.m8n8.x4.shared.b16 {%0,%1,%2,%3}, [%4];" \
        : "=r"(R[0]), "=r"(R[1]), "=r"(R[2]), "=r"(R[3]) : "r"(ADDR))
#define LDSM_X4T(R, ADDR) \
    asm volatile("ldmatrix.sync.aligned.m8n8.x4.trans.shared.b16 {%0,%1,%2,%3}, [%4];" \
        : "=r"(R[0]), "=r"(R[1]), "=r"(R[2]), "=r"(R[3]) : "r"(ADDR))

#define CP_ASYNC16(DST, SRC) \
    asm volatile("cp.async.cg.shared.global [%0], [%1], 16;" :: "r"(DST), "l"(SRC))
#define CP_COMMIT() asm volatile("cp.async.commit_group;")
#define CP_WAIT2()  asm volatile("cp.async.wait_group 2;")

// ---------------- dense bf16x3 GEMM, cp.async 4-stage pipeline ----------------
// smem (dynamic): As[4][128][40] bf16 then Bs[4][32][136] bf16 = 75776 bytes.
#define GEMM_SMEM (4*128*40*2 + 4*32*136*2)

__global__ __launch_bounds__(256) void gemm_bf16x3p(
    const __nv_bfloat16* __restrict__ A, const __nv_bfloat16* __restrict__ W,
    const float* __restrict__ bias, float* __restrict__ out, int N)
{
    extern __shared__ __nv_bfloat16 gsm[];
    __nv_bfloat16 (*As)[128][40] = (__nv_bfloat16(*)[128][40])gsm;
    __nv_bfloat16 (*Bs)[32][136] = (__nv_bfloat16(*)[32][136])(gsm + 4 * 128 * 40);

    const int n0 = blockIdx.x * 128;
    const int m0 = blockIdx.y * 128;
    const int tid = threadIdx.x;
    const int lane = tid & 31, w = tid >> 5;
    const int wm = (w >> 1) * 32, wn = (w & 1) * 64;
    const size_t ASTRIDE = (size_t)4096 * 1024;
    const size_t WSTRIDE = (size_t)1024 * N;

    float acc[2][8][4];
    #pragma unroll
    for (int mt = 0; mt < 2; mt++)
        #pragma unroll
        for (int nt = 0; nt < 8; nt++)
            #pragma unroll
            for (int i = 0; i < 4; i++) acc[mt][nt][i] = 0.0f;

    // cp.async assignments: 512 16B-chunks per tile, 2 per thread.
    auto issue = [&](int i, int st) {
        int r = i >> 5, sk = (i & 31) * 32;
        const __nv_bfloat16* Ap = A + (r == 2 ? ASTRIDE : 0);
        const __nv_bfloat16* Wp = W + (r == 1 ? WSTRIDE : 0);
        #pragma unroll
        for (int cc = 0; cc < 2; cc++) {
            int c = tid + cc * 256;
            int arow = c >> 2, akc = (c & 3) * 8;
            uint32_t da = (uint32_t)__cvta_generic_to_shared(&As[st][arow][akc]);
            CP_ASYNC16(da, Ap + (size_t)(m0 + arow) * 1024 + sk + akc);
            int brow = c >> 4, bnc = (c & 15) * 8;
            uint32_t db = (uint32_t)__cvta_generic_to_shared(&Bs[st][brow][bnc]);
            CP_ASYNC16(db, Wp + (size_t)(sk + brow) * N + n0 + bnc);
        }
        CP_COMMIT();
    };

    issue(0, 0); issue(1, 1); issue(2, 2);

    for (int i = 0; i < 96; i++) {
        CP_WAIT2();
        __syncthreads();
        const int st = i & 3;
        #pragma unroll
        for (int ks = 0; ks < 2; ks++) {
            const int k0 = ks * 16;
            uint32_t a[2][4], bb[4][4];
            #pragma unroll
            for (int mt = 0; mt < 2; mt++) {
                uint32_t sa = (uint32_t)__cvta_generic_to_shared(
                    &As[st][wm + mt * 16 + (lane & 15)][k0 + (lane >> 4) * 8]);
                LDSM_X4(a[mt], sa);
            }
            #pragma unroll
            for (int np = 0; np < 4; np++) {
                uint32_t sb = (uint32_t)__cvta_generic_to_shared(
                    &Bs[st][k0 + (lane & 15)][wn + np * 16 + (lane >> 4) * 8]);
                LDSM_X4T(bb[np], sb);
            }
            #pragma unroll
            for (int mt = 0; mt < 2; mt++)
                #pragma unroll
                for (int nt = 0; nt < 8; nt++)
                    MMA_BF16(acc[mt][nt], a[mt][0], a[mt][1], a[mt][2], a[mt][3],
                             bb[nt >> 1][(nt & 1) * 2], bb[nt >> 1][(nt & 1) * 2 + 1]);
        }
        if (i + 3 < 96) issue(i + 3, (i + 3) & 3);
        else CP_COMMIT();   // keep group-count invariant for wait_group 2
    }

    #pragma unroll
    for (int mt = 0; mt < 2; mt++) {
        #pragma unroll
        for (int nt = 0; nt < 8; nt++) {
            int row = m0 + wm + mt * 16 + (lane >> 2);
            int col = n0 + wn + nt * 8 + (lane & 3) * 2;
            float b0 = bias[col], b1 = bias[col + 1];
            float2 o0 = make_float2(acc[mt][nt][0] + b0, acc[mt][nt][1] + b1);
            float2 o1 = make_float2(acc[mt][nt][2] + b0, acc[mt][nt][3] + b1);
            *(float2*)(out + (size_t)row * N + col) = o0;
            *(float2*)(out + (size_t)(row + 8) * N + col) = o1;
        }
    }
}

// ---------------- lr2 ----------------
__global__ __launch_bounds__(256) void lr2_kernel(const float* __restrict__ LR_Q)
{
    __shared__ float LQ[64][64];
    __shared__ float Ks[64][65];
    const int bh = blockIdx.y;
    const int b = bh >> 4, h = bh & (H_ - 1);
    const int s0 = blockIdx.x * 64;
    const int tid = threadIdx.x;

    for (int it = 0; it < 16; it++) {
        int f = it * 256 + tid;
        LQ[f >> 6][f & 63] = LR_Q[(size_t)(h * 64 + (f >> 6)) * 64 + (f & 63)];
    }
    for (int it = 0; it < 16; it++) {
        int f = it * 256 + tid;
        Ks[f >> 6][f & 63] =
            g_qkv[(size_t)(b * T_ + s0 + (f >> 6)) * 3072 + 1024 + h * 64 + (f & 63)];
    }
    __syncthreads();

    const int s = tid & 63;
    const int g = tid >> 6;
    float acc[16];
    #pragma unroll
    for (int nn = 0; nn < 16; nn++) acc[nn] = 0.0f;
    for (int d = 0; d < 64; d++) {
        float kv = Ks[s][d];
        #pragma unroll
        for (int nn = 0; nn < 16; nn++) acc[nn] += LQ[g * 16 + nn][d] * kv;
    }
    #pragma unroll
    for (int nn = 0; nn < 16; nn++)
        g_lr2[(size_t)(bh * 64 + g * 16 + nn) * T_ + s0 + s] = acc[nn] * 0.125f;
}

// ---------------- fused attention: MMA, 2 CTAs/SM (unchanged from R11) ----------------
#define ATT_SMEM 112272

__global__ void __launch_bounds__(256, 2) attn_kernel(
    const int* __restrict__ rel, const float* __restrict__ tds,
    const float* __restrict__ LR_K, const int* __restrict__ LR_map,
    const float* __restrict__ rel_w_emb, const float* __restrict__ rel_k_emb,
    const float* __restrict__ rel_v_emb)
{
    extern __shared__ char smraw[];
    __nv_bfloat16* kh  = (__nv_bfloat16*)(smraw);
    __nv_bfloat16* kl  = kh + 64 * 72;
    __nv_bfloat16* vh  = kl + 64 * 72;
    __nv_bfloat16* vl  = vh + 64 * 72;
    __nv_bfloat16* qhp = (__nv_bfloat16*)(smraw);
    float*         lr2s = (float*)(smraw + 36864);
    __nv_bfloat16* pstg = (__nv_bfloat16*)(smraw + 54272);
    __nv_bfloat16* lr1  = (__nv_bfloat16*)(smraw + 71168);
    float*         qf   = (float*)(smraw + 54272);
    float*         qr   = (float*)(smraw + 88064);
    __nv_bfloat16* rvD  = (__nv_bfloat16*)(smraw + 107008);
    float*         rv0  = (float*)(smraw + 111760);
    float*         relw = (float*)(smraw + 112016);

    const int bid = blockIdx.x;
    const int rb = 7 - (bid >> 6);
    const int bh = bid & 63;
    const int t0 = rb * 128;
    const int b = bh >> 4, h = bh & 15;
    const int tid = threadIdx.x;
    const int lane = tid & 31, w = tid >> 5;
    const int r8 = lane >> 2, cp = lane & 3;
    const int tw = t0 + w * 16;
    const int lra = w * 16 + r8;
    const int ta = t0 + lra, tb2 = ta + 8;

    const float* qbase = g_qkv + (size_t)b * T_ * 3072 + h * 64;
    const float* kbase = qbase + 1024;
    const float* vbase = qbase + 2048;
    const float* lr2base = g_lr2 + (size_t)bh * NLOC_ * T_;
    const int* relbase = rel + (size_t)b * T_ * T_;
    const int* lmbase = LR_map + (size_t)b * T_ * T_;
    const float* tdsbase = tds + (size_t)bh * T_ * T_;

    for (int f = tid; f < 2048; f += 256) {
        int row = f >> 4, dq = (f & 15) * 4;
        float4 qv = *(const float4*)(qbase + (size_t)(t0 + row) * 3072 + dq);
        qf[row * 65 + dq + 0] = qv.x; qf[row * 65 + dq + 1] = qv.y;
        qf[row * 65 + dq + 2] = qv.z; qf[row * 65 + dq + 3] = qv.w;
    }
    if (tid < 64) { relw[tid] = rel_w_emb[tid * H_ + h]; rv0[tid] = rel_v_emb[tid]; }
    for (int f = tid; f < 33 * 64; f += 256) {
        int id = f >> 6, d = f & 63;
        rvD[id * 72 + d] = __float2bfloat16(rel_v_emb[id * 64 + d] - rel_v_emb[d]);
    }
    __syncthreads();

    for (int task = tid; task < 33 * 128; task += 256) {
        int id = task >> 7, lr = task & 127;
        const float* rk = rel_k_emb + id * 64;
        float a = 0.0f;
        #pragma unroll 8
        for (int d = 0; d < 64; d++) a += qf[lr * 65 + d] * rk[d];
        qr[lr * 37 + id] = a;
    }
    float lr1v[32];
    #pragma unroll
    for (int kk = 0; kk < 32; kk++) {
        int task = tid + kk * 256;
        int n = task >> 7, lr = task & 127;
        const float* lk = LR_K + (size_t)(h * 64 + n) * 64;
        float a = 0.0f;
        #pragma unroll 8
        for (int d = 0; d < 64; d++) a += qf[lr * 65 + d] * lk[d];
        lr1v[kk] = a * 0.125f;
    }
    for (int f = tid; f < 2048; f += 256) {
        int row = f >> 4, dq = (f & 15) * 4;
        __nv_bfloat162 h0, h1;
        h0.x = __float2bfloat16(qf[row * 65 + dq + 0]);
        h0.y = __float2bfloat16(qf[row * 65 + dq + 1]);
        h1.x = __float2bfloat16(qf[row * 65 + dq + 2]);
        h1.y = __float2bfloat16(qf[row * 65 + dq + 3]);
        *(uint32_t*)&qhp[row * 72 + dq]     = *(uint32_t*)&h0;
        *(uint32_t*)&qhp[row * 72 + dq + 2] = *(uint32_t*)&h1;
    }
    __syncthreads();
    #pragma unroll
    for (int kk = 0; kk < 32; kk++) {
        int task = tid + kk * 256;
        int n = task >> 7, lr = task & 127;
        lr1[lr * 66 + n] = __float2bfloat16(lr1v[kk]);
    }
    const int arow = w * 16 + (lane & 15);
    const int acol8 = (lane >> 4) * 8;
    uint32_t qfh[4][4];
    #pragma unroll
    for (int ks = 0; ks < 4; ks++) {
        uint32_t sa = (uint32_t)__cvta_generic_to_shared(
            &qhp[arow * 72 + ks * 16 + acol8]);
        LDSM_X4(qfh[ks], sa);
    }
    __syncthreads();

    const float qr0a = qr[lra * 37], qr0b = qr[(lra + 8) * 37];
    float m0 = -1e30f, m1 = -1e30f, l0_ = 0.0f, l1_ = 0.0f;
    float oacc[8][4];
    #pragma unroll
    for (int nt = 0; nt < 8; nt++)
        #pragma unroll
        for (int i = 0; i < 4; i++) oacc[nt][i] = 0.0f;

    const int nchunk = 2 * rb + 2;
    const int fs = tid >> 4, fdq = (tid & 15) * 4;

    for (int c = 0; c < nchunk; c++) {
        const int s0c = c * 64;
        __syncthreads();
        #pragma unroll
        for (int i = 0; i < 4; i++) {
            int s = fs + i * 16;
            float4 kv = *(const float4*)(kbase + (size_t)(s0c + s) * 3072 + fdq);
            float4 vv = *(const float4*)(vbase + (size_t)(s0c + s) * 3072 + fdq);
            float4 l2 = *(const float4*)(lr2base + (size_t)s * T_ + s0c + fdq);
            float ka[4] = {kv.x, kv.y, kv.z, kv.w};
            #pragma unroll
            for (int j = 0; j < 4; j++) {
                __nv_bfloat16 hh = __float2bfloat16(ka[j]);
                kh[(fdq + j) * 72 + s] = hh;
                kl[(fdq + j) * 72 + s] = __float2bfloat16(ka[j] - __bfloat162float(hh));
            }
            uint32_t vh0, vl0, vh1, vl1;
            packsplit(vv.x, vv.y, vh0, vl0);
            packsplit(vv.z, vv.w, vh1, vl1);
            *(uint32_t*)&vh[s * 72 + fdq]     = vh0;
            *(uint32_t*)&vh[s * 72 + fdq + 2] = vh1;
            *(uint32_t*)&vl[s * 72 + fdq]     = vl0;
            *(uint32_t*)&vl[s * 72 + fdq + 2] = vl1;
            *(float4*)&lr2s[s * 68 + fdq] = l2;
        }
        __syncthreads();

        if (s0c > tw + 15) continue;
        const bool far = (s0c + 96 <= tw);

        float sfr[8][4];
        #pragma unroll
        for (int nt = 0; nt < 8; nt++)
            #pragma unroll
            for (int i = 0; i < 4; i++) sfr[nt][i] = 0.0f;

        #pragma unroll
        for (int ks = 0; ks < 4; ks++) {
            const int k0 = ks * 16;
            #pragma unroll
            for (int ng = 0; ng < 4; ng++) {
                uint32_t bh_[4], bl_[4];
                uint32_t sb1 = (uint32_t)__cvta_generic_to_shared(
                    &kh[(k0 + (lane & 15)) * 72 + ng * 16 + acol8]);
                LDSM_X4T(bh_, sb1);
                uint32_t sb2 = (uint32_t)__cvta_generic_to_shared(
                    &kl[(k0 + (lane & 15)) * 72 + ng * 16 + acol8]);
                LDSM_X4T(bl_, sb2);
                const int nt0 = ng * 2;
                MMA_BF16(sfr[nt0],     qfh[ks][0], qfh[ks][1], qfh[ks][2], qfh[ks][3], bh_[0], bh_[1]);
                MMA_BF16(sfr[nt0 + 1], qfh[ks][0], qfh[ks][1], qfh[ks][2], qfh[ks][3], bh_[2], bh_[3]);
                MMA_BF16(sfr[nt0],     qfh[ks][0], qfh[ks][1], qfh[ks][2], qfh[ks][3], bl_[0], bl_[1]);
                MMA_BF16(sfr[nt0 + 1], qfh[ks][0], qfh[ks][1], qfh[ks][2], qfh[ks][3], bl_[2], bl_[3]);
            }
        }

        #pragma unroll
        for (int nt = 0; nt < 8; nt++) {
            const int sl0 = nt * 8 + cp * 2;
            const int sb_ = s0c + sl0;
            const size_t offA = (size_t)ta * T_ + sb_;
            const size_t offB = (size_t)tb2 * T_ + sb_;
            int2 rA = *(const int2*)(relbase + offA);
            int2 rB = *(const int2*)(relbase + offB);
            int2 lA = *(const int2*)(lmbase + offA);
            int2 lB = *(const int2*)(lmbase + offB);
            float2 tA = *(const float2*)(tdsbase + offA);
            float2 tB = *(const float2*)(tdsbase + offB);
            float qa0, qa1, qb0, qb1;
            if (far) { qa0 = qa1 = qr0a; qb0 = qb1 = qr0b; }
            else {
                int i0 = min(32, max(0, sb_ - ta + 32));
                int i1 = min(32, max(0, sb_ + 1 - ta + 32));
                int i2 = min(32, max(0, sb_ - tb2 + 32));
                int i3 = min(32, max(0, sb_ + 1 - tb2 + 32));
                qa0 = qr[lra * 37 + i0]; qa1 = qr[lra * 37 + i1];
                qb0 = qr[(lra + 8) * 37 + i2]; qb1 = qr[(lra + 8) * 37 + i3];
            }
            float x0 = fmaf((sfr[nt][0] + qa0) * 0.125f, relw[rA.x], tA.x)
                       + __bfloat162float(lr1[lra * 66 + lA.x]) + lr2s[lA.x * 68 + sl0];
            float x1 = fmaf((sfr[nt][1] + qa1) * 0.125f, relw[rA.y], tA.y)
                       + __bfloat162float(lr1[lra * 66 + lA.y]) + lr2s[lA.y * 68 + sl0 + 1];
            float x2 = fmaf((sfr[nt][2] + qb0) * 0.125f, relw[rB.x], tB.x)
                       + __bfloat162float(lr1[(lra + 8) * 66 + lB.x]) + lr2s[lB.x * 68 + sl0];
            float x3 = fmaf((sfr[nt][3] + qb1) * 0.125f, relw[rB.y], tB.y)
                       + __bfloat162float(lr1[(lra + 8) * 66 + lB.y]) + lr2s[lB.y * 68 + sl0 + 1];
            sfr[nt][0] = (sb_     > ta ) ? -1e30f : x0 * 0.70710678118f;
            sfr[nt][1] = (sb_ + 1 > ta ) ? -1e30f : x1 * 0.70710678118f;
            sfr[nt][2] = (sb_     > tb2) ? -1e30f : x2 * 0.70710678118f;
            sfr[nt][3] = (sb_ + 1 > tb2) ? -1e30f : x3 * 0.70710678118f;
        }

        float mxa = -1e30f, mxb = -1e30f;
        #pragma unroll
        for (int nt = 0; nt < 8; nt++) {
            mxa = fmaxf(mxa, fmaxf(sfr[nt][0], sfr[nt][1]));
            mxb = fmaxf(mxb, fmaxf(sfr[nt][2], sfr[nt][3]));
        }
        mxa = fmaxf(mxa, __shfl_xor_sync(0xffffffffu, mxa, 1));
        mxa = fmaxf(mxa, __shfl_xor_sync(0xffffffffu, mxa, 2));
        mxb = fmaxf(mxb, __shfl_xor_sync(0xffffffffu, mxb, 1));
        mxb = fmaxf(mxb, __shfl_xor_sync(0xffffffffu, mxb, 2));
        float mna = fmaxf(m0, mxa), sc0 = fast_exp(m0 - mna);
        float mnb = fmaxf(m1, mxb), sc1 = fast_exp(m1 - mnb);
        float pa = 0.0f, pb = 0.0f;
        #pragma unroll
        for (int nt = 0; nt < 8; nt++) {
            sfr[nt][0] = fast_exp(sfr[nt][0] - mna);
            sfr[nt][1] = fast_exp(sfr[nt][1] - mna);
            sfr[nt][2] = fast_exp(sfr[nt][2] - mnb);
            sfr[nt][3] = fast_exp(sfr[nt][3] - mnb);
            pa += sfr[nt][0] + sfr[nt][1];
            pb += sfr[nt][2] + sfr[nt][3];
        }
        pa += __shfl_xor_sync(0xffffffffu, pa, 1);
        pa += __shfl_xor_sync(0xffffffffu, pa, 2);
        pb += __shfl_xor_sync(0xffffffffu, pb, 1);
        pb += __shfl_xor_sync(0xffffffffu, pb, 2);
        l0_ = l0_ * sc0 + pa; m0 = mna;
        l1_ = l1_ * sc1 + pb; m1 = mnb;
        #pragma unroll
        for (int nt = 0; nt < 8; nt++) {
            oacc[nt][0] *= sc0; oacc[nt][1] *= sc0;
            oacc[nt][2] *= sc1; oacc[nt][3] *= sc1;
        }

        if (!far) {
            #pragma unroll
            for (int nt = 0; nt < 8; nt++) {
                int sl0 = nt * 8 + cp * 2;
                pstg[lra * 66 + sl0]           = __float2bfloat16(sfr[nt][0]);
                pstg[lra * 66 + sl0 + 1]       = __float2bfloat16(sfr[nt][1]);
                pstg[(lra + 8) * 66 + sl0]     = __float2bfloat16(sfr[nt][2]);
                pstg[(lra + 8) * 66 + sl0 + 1] = __float2bfloat16(sfr[nt][3]);
            }
        }

        uint32_t ph[4][4], pl2[4][4];
        #pragma unroll
        for (int kk = 0; kk < 4; kk++) {
            packsplit(sfr[2*kk][0],   sfr[2*kk][1],   ph[kk][0], pl2[kk][0]);
            packsplit(sfr[2*kk][2],   sfr[2*kk][3],   ph[kk][1], pl2[kk][1]);
            packsplit(sfr[2*kk+1][0], sfr[2*kk+1][1], ph[kk][2], pl2[kk][2]);
            packsplit(sfr[2*kk+1][2], sfr[2*kk+1][3], ph[kk][3], pl2[kk][3]);
        }

        #pragma unroll
        for (int kk = 0; kk < 4; kk++) {
            const int k0 = kk * 16;
            #pragma unroll
            for (int ng = 0; ng < 4; ng++) {
                uint32_t bb[4];
                uint32_t sb = (uint32_t)__cvta_generic_to_shared(
                    &vh[(k0 + (lane & 15)) * 72 + ng * 16 + acol8]);
                LDSM_X4T(bb, sb);
                const int nt0 = ng * 2;
                MMA_BF16(oacc[nt0],     ph[kk][0], ph[kk][1], ph[kk][2], ph[kk][3], bb[0], bb[1]);
                MMA_BF16(oacc[nt0 + 1], ph[kk][0], ph[kk][1], ph[kk][2], ph[kk][3], bb[2], bb[3]);
                MMA_BF16(oacc[nt0],     pl2[kk][0], pl2[kk][1], pl2[kk][2], pl2[kk][3], bb[0], bb[1]);
                MMA_BF16(oacc[nt0 + 1], pl2[kk][0], pl2[kk][1], pl2[kk][2], pl2[kk][3], bb[2], bb[3]);
            }
        }
        #pragma unroll
        for (int kk = 0; kk < 4; kk++) {
            const int k0 = kk * 16;
            #pragma unroll
            for (int ng = 0; ng < 4; ng++) {
                uint32_t bb[4];
                uint32_t sb = (uint32_t)__cvta_generic_to_shared(
                    &vl[(k0 + (lane & 15)) * 72 + ng * 16 + acol8]);
                LDSM_X4T(bb, sb);
                const int nt0 = ng * 2;
                MMA_BF16(oacc[nt0],     ph[kk][0], ph[kk][1], ph[kk][2], ph[kk][3], bb[0], bb[1]);
                MMA_BF16(oacc[nt0 + 1], ph[kk][0], ph[kk][1], ph[kk][2], ph[kk][3], bb[2], bb[3]);
            }
        }

        if (!far) {
            __syncwarp();
            #pragma unroll
            for (int rsel = 0; rsel < 2; rsel++) {
                const int t = rsel ? tb2 : ta;
                const __nv_bfloat16* Prow = pstg + (size_t)(lra + rsel * 8) * 66;
                for (int j = 0; j <= 32; j++) {
                    int sl = t - 32 + j - s0c;
                    if (sl < 0 || sl > 63) continue;
                    float p = __bfloat162float(Prow[sl]);
                    #pragma unroll
                    for (int nt = 0; nt < 8; nt++) {
                        uint32_t rvu = *(const uint32_t*)&rvD[j * 72 + nt * 8 + cp * 2];
                        __nv_bfloat162 rv2 = *(__nv_bfloat162*)&rvu;
                        oacc[nt][rsel * 2 + 0] += p * __bfloat162float(rv2.x);
                        oacc[nt][rsel * 2 + 1] += p * __bfloat162float(rv2.y);
                    }
                }
            }
        }
    }

    const float invl0 = 1.0f / l0_, invl1 = 1.0f / l1_;
    #pragma unroll
    for (int rsel = 0; rsel < 2; rsel++) {
        const int t = rsel ? tb2 : ta;
        const float invl = rsel ? invl1 : invl0;
        #pragma unroll
        for (int nt = 0; nt < 8; nt++) {
            int c0 = nt * 8 + cp * 2;
            float o0 = oacc[nt][rsel * 2 + 0] * invl + rv0[c0];
            float o1 = oacc[nt][rsel * 2 + 1] * invl + rv0[c0 + 1];
            uint32_t hp, lp;
            packsplit(o0, o1, hp, lp);
            size_t oidx = (size_t)(b * T_ + t) * NX_ + h * 64 + c0;
            *(uint32_t*)&g_atts[0][oidx] = hp;
            *(uint32_t*)&g_atts[1][oidx] = lp;
        }
    }
}

// ---------------- launch ----------------
extern "C" void kernel_launch(void* const* d_in, const int* in_sizes, int n_in,
                              void* d_out, int out_size)
{
    const float* x          = (const float*)d_in[0];
    const int*   rel        = (const int*)  d_in[1];
    const float* tds        = (const float*)d_in[2];
    const float* LR_Q       = (const float*)d_in[3];
    const float* LR_K       = (const float*)d_in[4];
    const int*   LR_map     = (const int*)  d_in[5];
    const float* c_attn_w   = (const float*)d_in[6];
    const float* c_attn_b   = (const float*)d_in[7];
    const float* c_proj_w   = (const float*)d_in[8];
    const float* c_proj_b   = (const float*)d_in[9];
    const float* rel_w_emb  = (const float*)d_in[10];
    const float* rel_k_emb  = (const float*)d_in[11];
    const float* rel_v_emb  = (const float*)d_in[12];
    float* out = (float*)d_out;

    cudaFuncSetAttribute(attn_kernel, cudaFuncAttributeMaxDynamicSharedMemorySize,
                         ATT_SMEM);
    cudaFuncSetAttribute(gemm_bf16x3p, cudaFuncAttributeMaxDynamicSharedMemorySize,
                         GEMM_SMEM);

    __nv_bfloat16 *xs, *w1s, *w2s, *atts;
    cudaGetSymbolAddress((void**)&xs, g_xs);
    cudaGetSymbolAddress((void**)&w1s, g_w1s);
    cudaGetSymbolAddress((void**)&w2s, g_w2s);
    cudaGetSymbolAddress((void**)&atts, g_atts);
    float* qkv_buf; cudaGetSymbolAddress((void**)&qkv_buf, g_qkv);

    const int NXM = B_ * T_ * NX_;
    split_kernel<<<NXM / 1024, 256>>>(x, xs, xs + NXM, NXM / 4);
    split_kernel<<<(NX_*3*NX_) / 1024, 256>>>(c_attn_w, w1s, w1s + NX_*3*NX_, (NX_*3*NX_) / 4);
    split_kernel<<<(NX_*NX_) / 1024, 256>>>(c_proj_w, w2s, w2s + NX_*NX_, (NX_*NX_) / 4);

    gemm_bf16x3p<<<dim3(24, 32), 256, GEMM_SMEM>>>(xs, w1s, c_attn_b, qkv_buf, 3072);
    lr2_kernel<<<dim3(16, 64), 256>>>(LR_Q);
    attn_kernel<<<512, 256, ATT_SMEM>>>(
        rel, tds, LR_K, LR_map, rel_w_emb, rel_k_emb, rel_v_emb);
    gemm_bf16x3p<<<dim3(8, 32), 256, GEMM_SMEM>>>(atts, w2s, c_proj_b, out, 1024);
}

// round 14
// speedup vs baseline: 1.0600x; 1.0529x over previous
#include <cuda_runtime.h>
#include <cuda_bf16.h>
#include <stdint.h>

#define B_ 4
#define T_ 1024
#define NX_ 1024
#define H_ 16
#define D_ 64
#define NLOC_ 64

__device__ __nv_bfloat16 g_xs[2][B_*T_*NX_];
__device__ __nv_bfloat16 g_w1s[2][NX_*3*NX_];
__device__ __nv_bfloat16 g_w2s[2][NX_*NX_];
__device__ __nv_bfloat16 g_atts[2][B_*T_*NX_];
__device__ __nv_bfloat16 g_khs[2][B_*H_*T_*D_];   // k hi/lo planes [bh][s][d]
__device__ __nv_bfloat16 g_vhs[2][B_*H_*T_*D_];   // v hi/lo planes
__device__ float g_qkv[B_*T_*3*NX_];              // only q slots used
__device__ float g_lr2[B_*H_*NLOC_*T_];

__device__ __forceinline__ float fast_exp(float x) {
    x = fmaxf(x, -80.0f);
    float t = x * 1.44269504088896341f;
    float z = t + 12582912.0f;
    int   ki = __float_as_int(z) - 0x4B400000;
    float f = t - (z - 12582912.0f);
    float p = 0.00133335581f;
    p = fmaf(p, f, 0.00961812910f);
    p = fmaf(p, f, 0.05550410866f);
    p = fmaf(p, f, 0.24022650696f);
    p = fmaf(p, f, 0.69314718056f);
    p = fmaf(p, f, 1.0f);
    return __int_as_float(__float_as_int(p) + (ki << 23));
}

__device__ __forceinline__ void packsplit(float x, float y, uint32_t& hi, uint32_t& lo) {
    __nv_bfloat162 h, l;
    h.x = __float2bfloat16(x); h.y = __float2bfloat16(y);
    l.x = __float2bfloat16(x - __bfloat162float(h.x));
    l.y = __float2bfloat16(y - __bfloat162float(h.y));
    hi = *(uint32_t*)&h; lo = *(uint32_t*)&l;
}

__global__ __launch_bounds__(256) void split_kernel(
    const float* __restrict__ in, __nv_bfloat16* __restrict__ hi,
    __nv_bfloat16* __restrict__ lo, int n4)
{
    int i = blockIdx.x * 256 + threadIdx.x;
    if (i >= n4) return;
    float4 v = *(const float4*)(in + i * 4);
    uint32_t h0, l0, h1, l1;
    packsplit(v.x, v.y, h0, l0);
    packsplit(v.z, v.w, h1, l1);
    *(uint2*)(hi + i * 4) = make_uint2(h0, h1);
    *(uint2*)(lo + i * 4) = make_uint2(l0, l1);
}

#define MMA_BF16(D, A0,A1,A2,A3, B0,B1) \
    asm volatile("mma.sync.aligned.m16n8k16.row.col.f32.bf16.bf16.f32 " \
        "{%0,%1,%2,%3},{%4,%5,%6,%7},{%8,%9},{%0,%1,%2,%3};" \
        : "+f"(D[0]), "+f"(D[1]), "+f"(D[2]), "+f"(D[3]) \
        : "r"(A0), "r"(A1), "r"(A2), "r"(A3), "r"(B0), "r"(B1))
#define LDSM_X4(R, ADDR) \
    asm volatile("ldmatrix.sync.aligned.m8n8.x4.shared.b16 {%0,%1,%2,%3}, [%4];" \
        : "=r"(R[0]), "=r"(R[1]), "=r"(R[2]), "=r"(R[3]) : "r"(ADDR))
#define LDSM_X4T(R, ADDR) \
    asm volatile("ldmatrix.sync.aligned.m8n8.x4.trans.shared.b16 {%0,%1,%2,%3}, [%4];" \
        : "=r"(R[0]), "=r"(R[1]), "=r"(R[2]), "=r"(R[3]) : "r"(ADDR))
#define CP_ASYNC16(DST, SRC) \
    asm volatile("cp.async.cg.shared.global [%0], [%1], 16;" :: "r"(DST), "l"(SRC))
#define CP_COMMIT() asm volatile("cp.async.commit_group;")
#define CP_WAIT0()  asm volatile("cp.async.wait_group 0;")

// ---------------- dense bf16x3 GEMM (R11 core + qkv-mode epilogue) ----------------
__global__ __launch_bounds__(256) void gemm_bf16x3s(
    const __nv_bfloat16* __restrict__ A, const __nv_bfloat16* __restrict__ W,
    const float* __restrict__ bias, float* __restrict__ out, int N, int qkv_mode)
{
    __shared__ __nv_bfloat16 As[2][128][40];
    __shared__ __nv_bfloat16 Bs[2][32][136];
    const int n0 = blockIdx.x * 128;
    const int m0 = blockIdx.y * 128;
    const int tid = threadIdx.x;
    const int lane = tid & 31, w = tid >> 5;
    const int wm = (w >> 1) * 32, wn = (w & 1) * 64;
    const size_t ASTRIDE = (size_t)4096 * 1024;
    const size_t WSTRIDE = (size_t)1024 * N;

    float acc[2][8][4];
    #pragma unroll
    for (int mt = 0; mt < 2; mt++)
        #pragma unroll
        for (int nt = 0; nt < 8; nt++)
            #pragma unroll
            for (int i = 0; i < 4; i++) acc[mt][nt][i] = 0.0f;

    const int ar0 = tid >> 2, ac0 = (tid & 3) * 8;
    const int br0 = tid >> 4, bc0 = (tid & 15) * 8;
    uint4 Ar[2], Br[2];

    auto ldg = [&](int i) {
        int r = i >> 5, sk = (i & 31) * 32;
        const __nv_bfloat16* Ap = A + (r == 2 ? ASTRIDE : 0);
        const __nv_bfloat16* Wp = W + (r == 1 ? WSTRIDE : 0);
        Ar[0] = *(const uint4*)(Ap + (size_t)(m0 + ar0) * 1024 + sk + ac0);
        Ar[1] = *(const uint4*)(Ap + (size_t)(m0 + ar0 + 64) * 1024 + sk + ac0);
        Br[0] = *(const uint4*)(Wp + (size_t)(sk + br0) * N + n0 + bc0);
        Br[1] = *(const uint4*)(Wp + (size_t)(sk + br0 + 16) * N + n0 + bc0);
    };
    auto sts = [&](int buf) {
        *(uint2*)&As[buf][ar0][ac0]      = make_uint2(Ar[0].x, Ar[0].y);
        *(uint2*)&As[buf][ar0][ac0 + 4]  = make_uint2(Ar[0].z, Ar[0].w);
        *(uint2*)&As[buf][ar0 + 64][ac0]     = make_uint2(Ar[1].x, Ar[1].y);
        *(uint2*)&As[buf][ar0 + 64][ac0 + 4] = make_uint2(Ar[1].z, Ar[1].w);
        *(uint4*)&Bs[buf][br0][bc0]      = Br[0];
        *(uint4*)&Bs[buf][br0 + 16][bc0] = Br[1];
    };

    ldg(0); sts(0);
    __syncthreads();

    int buf = 0;
    for (int i = 0; i < 96; i++) {
        if (i + 1 < 96) ldg(i + 1);
        #pragma unroll
        for (int ks = 0; ks < 2; ks++) {
            const int k0 = ks * 16;
            uint32_t a[2][4], bb[4][4];
            #pragma unroll
            for (int mt = 0; mt < 2; mt++) {
                uint32_t sa = (uint32_t)__cvta_generic_to_shared(
                    &As[buf][wm + mt * 16 + (lane & 15)][k0 + (lane >> 4) * 8]);
                LDSM_X4(a[mt], sa);
            }
            #pragma unroll
            for (int np = 0; np < 4; np++) {
                uint32_t sb = (uint32_t)__cvta_generic_to_shared(
                    &Bs[buf][k0 + (lane & 15)][wn + np * 16 + (lane >> 4) * 8]);
                LDSM_X4T(bb[np], sb);
            }
            #pragma unroll
            for (int mt = 0; mt < 2; mt++)
                #pragma unroll
                for (int nt = 0; nt < 8; nt++)
                    MMA_BF16(acc[mt][nt], a[mt][0], a[mt][1], a[mt][2], a[mt][3],
                             bb[nt >> 1][(nt & 1) * 2], bb[nt >> 1][(nt & 1) * 2 + 1]);
        }
        if (i + 1 < 96) {
            int nb = buf ^ 1;
            sts(nb);
        }
        __syncthreads();
        buf ^= 1;
    }

    #pragma unroll
    for (int mt = 0; mt < 2; mt++) {
        #pragma unroll
        for (int nt = 0; nt < 8; nt++) {
            int row = m0 + wm + mt * 16 + (lane >> 2);
            int col = n0 + wn + nt * 8 + (lane & 3) * 2;
            float b0 = bias[col], b1 = bias[col + 1];
            float v00 = acc[mt][nt][0] + b0, v01 = acc[mt][nt][1] + b1;
            float v10 = acc[mt][nt][2] + b0, v11 = acc[mt][nt][3] + b1;
            if (!qkv_mode) {
                *(float2*)(out + (size_t)row * N + col) = make_float2(v00, v01);
                *(float2*)(out + (size_t)(row + 8) * N + col) = make_float2(v10, v11);
            } else {
                int which = col >> 10, cc = col & 1023;
                int hh = cc >> 6, dd = cc & 63;
                int b0i = row >> 10, t0i = row & 1023;
                if (which == 0) {
                    *(float2*)(out + (size_t)row * 3072 + col) = make_float2(v00, v01);
                    *(float2*)(out + (size_t)(row + 8) * 3072 + col) = make_float2(v10, v11);
                } else {
                    __nv_bfloat16* ph = (which == 1) ? g_khs[0] : g_vhs[0];
                    __nv_bfloat16* pl = (which == 1) ? g_khs[1] : g_vhs[1];
                    size_t o0 = ((size_t)(b0i * H_ + hh) * T_ + t0i) * 64 + dd;
                    size_t o1 = o0 + 8 * 64;
                    uint32_t hi, lo;
                    packsplit(v00, v01, hi, lo);
                    *(uint32_t*)&ph[o0] = hi; *(uint32_t*)&pl[o0] = lo;
                    packsplit(v10, v11, hi, lo);
                    *(uint32_t*)&ph[o1] = hi; *(uint32_t*)&pl[o1] = lo;
                }
            }
        }
    }
}

// ---------------- lr2 (reads k planes) ----------------
__global__ __launch_bounds__(256) void lr2_kernel(const float* __restrict__ LR_Q)
{
    __shared__ float LQ[64][64];
    __shared__ float Ks[64][65];
    const int bh = blockIdx.y;
    const int h = bh & (H_ - 1);
    const int s0 = blockIdx.x * 64;
    const int tid = threadIdx.x;

    for (int it = 0; it < 16; it++) {
        int f = it * 256 + tid;
        LQ[f >> 6][f & 63] = LR_Q[(size_t)(h * 64 + (f >> 6)) * 64 + (f & 63)];
    }
    for (int it = 0; it < 16; it++) {
        int f = it * 256 + tid;
        size_t off = ((size_t)bh * T_ + s0 + (f >> 6)) * 64 + (f & 63);
        Ks[f >> 6][f & 63] = __bfloat162float(g_khs[0][off]) + __bfloat162float(g_khs[1][off]);
    }
    __syncthreads();

    const int s = tid & 63;
    const int g = tid >> 6;
    float acc[16];
    #pragma unroll
    for (int nn = 0; nn < 16; nn++) acc[nn] = 0.0f;
    for (int d = 0; d < 64; d++) {
        float kv = Ks[s][d];
        #pragma unroll
        for (int nn = 0; nn < 16; nn++) acc[nn] += LQ[g * 16 + nn][d] * kv;
    }
    #pragma unroll
    for (int nn = 0; nn < 16; nn++)
        g_lr2[(size_t)(bh * 64 + g * 16 + nn) * T_ + s0 + s] = acc[nn] * 0.125f;
}

// ---------------- fused attention: MMA, 2 CTAs/SM, cp.async fills ----------------
// smem layout identical sizes to R11; kh/kl now [s][72] (QK uses non-trans ldmatrix).
#define ATT_SMEM 112272

__global__ void __launch_bounds__(256, 2) attn_kernel(
    const int* __restrict__ rel, const float* __restrict__ tds,
    const float* __restrict__ LR_K, const int* __restrict__ LR_map,
    const float* __restrict__ rel_w_emb, const float* __restrict__ rel_k_emb,
    const float* __restrict__ rel_v_emb)
{
    extern __shared__ char smraw[];
    __nv_bfloat16* kh  = (__nv_bfloat16*)(smraw);          // [64 s][72]
    __nv_bfloat16* kl  = kh + 64 * 72;
    __nv_bfloat16* vh  = kl + 64 * 72;                     // [64 s][72]
    __nv_bfloat16* vl  = vh + 64 * 72;
    __nv_bfloat16* qhp = (__nv_bfloat16*)(smraw);          // prologue alias
    float*         lr2s = (float*)(smraw + 36864);         // [64][68]
    __nv_bfloat16* pstg = (__nv_bfloat16*)(smraw + 54272); // [128][66]
    __nv_bfloat16* lr1  = (__nv_bfloat16*)(smraw + 71168); // [128][66]
    float*         qf   = (float*)(smraw + 54272);         // [128][65] prologue
    float*         qr   = (float*)(smraw + 88064);         // [128][37]
    __nv_bfloat16* rvD  = (__nv_bfloat16*)(smraw + 107008);// [33][72]
    float*         rv0  = (float*)(smraw + 111760);
    float*         relw = (float*)(smraw + 112016);

    const int bid = blockIdx.x;
    const int rb = 7 - (bid >> 6);
    const int bh = bid & 63;
    const int t0 = rb * 128;
    const int b = bh >> 4, h = bh & 15;
    const int tid = threadIdx.x;
    const int lane = tid & 31, w = tid >> 5;
    const int r8 = lane >> 2, cp = lane & 3;
    const int tw = t0 + w * 16;
    const int lra = w * 16 + r8;
    const int ta = t0 + lra, tb2 = ta + 8;

    const float* qbase = g_qkv + (size_t)b * T_ * 3072 + h * 64;
    const __nv_bfloat16* khp = g_khs[0] + (size_t)bh * T_ * 64;
    const __nv_bfloat16* klp = g_khs[1] + (size_t)bh * T_ * 64;
    const __nv_bfloat16* vhp = g_vhs[0] + (size_t)bh * T_ * 64;
    const __nv_bfloat16* vlp = g_vhs[1] + (size_t)bh * T_ * 64;
    const float* lr2base = g_lr2 + (size_t)bh * NLOC_ * T_;
    const int* relbase = rel + (size_t)b * T_ * T_;
    const int* lmbase = LR_map + (size_t)b * T_ * T_;
    const float* tdsbase = tds + (size_t)bh * T_ * T_;

    // ---- prologue ----
    for (int f = tid; f < 2048; f += 256) {
        int row = f >> 4, dq = (f & 15) * 4;
        float4 qv = *(const float4*)(qbase + (size_t)(t0 + row) * 3072 + dq);
        qf[row * 65 + dq + 0] = qv.x; qf[row * 65 + dq + 1] = qv.y;
        qf[row * 65 + dq + 2] = qv.z; qf[row * 65 + dq + 3] = qv.w;
    }
    if (tid < 64) { relw[tid] = rel_w_emb[tid * H_ + h]; rv0[tid] = rel_v_emb[tid]; }
    for (int f = tid; f < 33 * 64; f += 256) {
        int id = f >> 6, d = f & 63;
        rvD[id * 72 + d] = __float2bfloat16(rel_v_emb[id * 64 + d] - rel_v_emb[d]);
    }
    __syncthreads();

    for (int task = tid; task < 33 * 128; task += 256) {
        int id = task >> 7, lr = task & 127;
        const float* rk = rel_k_emb + id * 64;
        float a = 0.0f;
        #pragma unroll 8
        for (int d = 0; d < 64; d++) a += qf[lr * 65 + d] * rk[d];
        qr[lr * 37 + id] = a;
    }
    float lr1v[32];
    #pragma unroll
    for (int kk = 0; kk < 32; kk++) {
        int task = tid + kk * 256;
        int n = task >> 7, lr = task & 127;
        const float* lk = LR_K + (size_t)(h * 64 + n) * 64;
        float a = 0.0f;
        #pragma unroll 8
        for (int d = 0; d < 64; d++) a += qf[lr * 65 + d] * lk[d];
        lr1v[kk] = a * 0.125f;
    }
    for (int f = tid; f < 2048; f += 256) {
        int row = f >> 4, dq = (f & 15) * 4;
        __nv_bfloat162 h0, h1;
        h0.x = __float2bfloat16(qf[row * 65 + dq + 0]);
        h0.y = __float2bfloat16(qf[row * 65 + dq + 1]);
        h1.x = __float2bfloat16(qf[row * 65 + dq + 2]);
        h1.y = __float2bfloat16(qf[row * 65 + dq + 3]);
        *(uint32_t*)&qhp[row * 72 + dq]     = *(uint32_t*)&h0;
        *(uint32_t*)&qhp[row * 72 + dq + 2] = *(uint32_t*)&h1;
    }
    __syncthreads();
    #pragma unroll
    for (int kk = 0; kk < 32; kk++) {
        int task = tid + kk * 256;
        int n = task >> 7, lr = task & 127;
        lr1[lr * 66 + n] = __float2bfloat16(lr1v[kk]);
    }
    const int arow = w * 16 + (lane & 15);
    const int acol8 = (lane >> 4) * 8;
    uint32_t qfh[4][4];
    #pragma unroll
    for (int ks = 0; ks < 4; ks++) {
        uint32_t sa = (uint32_t)__cvta_generic_to_shared(
            &qhp[arow * 72 + ks * 16 + acol8]);
        LDSM_X4(qfh[ks], sa);
    }
    __syncthreads();

    const float qr0a = qr[lra * 37], qr0b = qr[(lra + 8) * 37];
    float m0 = -1e30f, m1 = -1e30f, l0_ = 0.0f, l1_ = 0.0f;
    float oacc[8][4];
    #pragma unroll
    for (int nt = 0; nt < 8; nt++)
        #pragma unroll
        for (int i = 0; i < 4; i++) oacc[nt][i] = 0.0f;

    // QK B-operand non-trans ldmatrix row/col (kh is [s][d]):
    const int mi = lane >> 3;
    const int bnrow = (lane & 7) + ((mi >> 1) << 3);   // n-row within 16-group
    const int bkcol = (mi & 1) << 3;                    // k-col half

    const int nchunk = 2 * rb + 2;

    for (int c = 0; c < nchunk; c++) {
        const int s0c = c * 64;
        __syncthreads();                        // buffer free
        // ---- cp.async fill: kh/kl/vh/vl (bf16 planes) + lr2s ----
        #pragma unroll
        for (int cc = 0; cc < 2; cc++) {
            int q = tid + cc * 256;             // 512 chunks per array
            int s = q >> 3, doff = (q & 7) * 8;
            const size_t go = (size_t)(s0c + s) * 64 + doff;
            CP_ASYNC16((uint32_t)__cvta_generic_to_shared(&kh[s * 72 + doff]), khp + go);
            CP_ASYNC16((uint32_t)__cvta_generic_to_shared(&kl[s * 72 + doff]), klp + go);
            CP_ASYNC16((uint32_t)__cvta_generic_to_shared(&vh[s * 72 + doff]), vhp + go);
            CP_ASYNC16((uint32_t)__cvta_generic_to_shared(&vl[s * 72 + doff]), vlp + go);
        }
        #pragma unroll
        for (int cc = 0; cc < 4; cc++) {
            int q = tid + cc * 256;             // 1024 chunks
            int s = q >> 4, off = (q & 15) * 4;
            CP_ASYNC16((uint32_t)__cvta_generic_to_shared(&lr2s[s * 68 + off]),
                       lr2base + (size_t)s * T_ + s0c + off);
        }
        CP_COMMIT();
        CP_WAIT0();
        __syncthreads();

        if (s0c > tw + 15) continue;
        const bool far = (s0c + 96 <= tw);

        // ---- QK (non-trans B from [s][d]) ----
        float sfr[8][4];
        #pragma unroll
        for (int nt = 0; nt < 8; nt++)
            #pragma unroll
            for (int i = 0; i < 4; i++) sfr[nt][i] = 0.0f;

        #pragma unroll
        for (int ks = 0; ks < 4; ks++) {
            const int k0 = ks * 16;
            #pragma unroll
            for (int ng = 0; ng < 4; ng++) {
                uint32_t bh_[4], bl_[4];
                uint32_t a1 = (uint32_t)__cvta_generic_to_shared(
                    &kh[(ng * 16 + bnrow) * 72 + k0 + bkcol]);
                LDSM_X4(bh_, a1);
                uint32_t a2 = (uint32_t)__cvta_generic_to_shared(
                    &kl[(ng * 16 + bnrow) * 72 + k0 + bkcol]);
                LDSM_X4(bl_, a2);
                const int nt0 = ng * 2;
                MMA_BF16(sfr[nt0],     qfh[ks][0], qfh[ks][1], qfh[ks][2], qfh[ks][3], bh_[0], bh_[1]);
                MMA_BF16(sfr[nt0 + 1], qfh[ks][0], qfh[ks][1], qfh[ks][2], qfh[ks][3], bh_[2], bh_[3]);
                MMA_BF16(sfr[nt0],     qfh[ks][0], qfh[ks][1], qfh[ks][2], qfh[ks][3], bl_[0], bl_[1]);
                MMA_BF16(sfr[nt0 + 1], qfh[ks][0], qfh[ks][1], qfh[ks][2], qfh[ks][3], bl_[2], bl_[3]);
            }
        }

        // ---- bias + mask ----
        #pragma unroll
        for (int nt = 0; nt < 8; nt++) {
            const int sl0 = nt * 8 + cp * 2;
            const int sb_ = s0c + sl0;
            const size_t offA = (size_t)ta * T_ + sb_;
            const size_t offB = (size_t)tb2 * T_ + sb_;
            int2 rA = *(const int2*)(relbase + offA);
            int2 rB = *(const int2*)(relbase + offB);
            int2 lA = *(const int2*)(lmbase + offA);
            int2 lB = *(const int2*)(lmbase + offB);
            float2 tA = *(const float2*)(tdsbase + offA);
            float2 tB = *(const float2*)(tdsbase + offB);
            float qa0, qa1, qb0, qb1;
            if (far) { qa0 = qa1 = qr0a; qb0 = qb1 = qr0b; }
            else {
                int i0 = min(32, max(0, sb_ - ta + 32));
                int i1 = min(32, max(0, sb_ + 1 - ta + 32));
                int i2 = min(32, max(0, sb_ - tb2 + 32));
                int i3 = min(32, max(0, sb_ + 1 - tb2 + 32));
                qa0 = qr[lra * 37 + i0]; qa1 = qr[lra * 37 + i1];
                qb0 = qr[(lra + 8) * 37 + i2]; qb1 = qr[(lra + 8) * 37 + i3];
            }
            float x0 = fmaf((sfr[nt][0] + qa0) * 0.125f, relw[rA.x], tA.x)
                       + __bfloat162float(lr1[lra * 66 + lA.x]) + lr2s[lA.x * 68 + sl0];
            float x1 = fmaf((sfr[nt][1] + qa1) * 0.125f, relw[rA.y], tA.y)
                       + __bfloat162float(lr1[lra * 66 + lA.y]) + lr2s[lA.y * 68 + sl0 + 1];
            float x2 = fmaf((sfr[nt][2] + qb0) * 0.125f, relw[rB.x], tB.x)
                       + __bfloat162float(lr1[(lra + 8) * 66 + lB.x]) + lr2s[lB.x * 68 + sl0];
            float x3 = fmaf((sfr[nt][3] + qb1) * 0.125f, relw[rB.y], tB.y)
                       + __bfloat162float(lr1[(lra + 8) * 66 + lB.y]) + lr2s[lB.y * 68 + sl0 + 1];
            sfr[nt][0] = (sb_     > ta ) ? -1e30f : x0 * 0.70710678118f;
            sfr[nt][1] = (sb_ + 1 > ta ) ? -1e30f : x1 * 0.70710678118f;
            sfr[nt][2] = (sb_     > tb2) ? -1e30f : x2 * 0.70710678118f;
            sfr[nt][3] = (sb_ + 1 > tb2) ? -1e30f : x3 * 0.70710678118f;
        }

        // ---- online softmax ----
        float mxa = -1e30f, mxb = -1e30f;
        #pragma unroll
        for (int nt = 0; nt < 8; nt++) {
            mxa = fmaxf(mxa, fmaxf(sfr[nt][0], sfr[nt][1]));
            mxb = fmaxf(mxb, fmaxf(sfr[nt][2], sfr[nt][3]));
        }
        mxa = fmaxf(mxa, __shfl_xor_sync(0xffffffffu, mxa, 1));
        mxa = fmaxf(mxa, __shfl_xor_sync(0xffffffffu, mxa, 2));
        mxb = fmaxf(mxb, __shfl_xor_sync(0xffffffffu, mxb, 1));
        mxb = fmaxf(mxb, __shfl_xor_sync(0xffffffffu, mxb, 2));
        float mna = fmaxf(m0, mxa), sc0 = fast_exp(m0 - mna);
        float mnb = fmaxf(m1, mxb), sc1 = fast_exp(m1 - mnb);
        float pa = 0.0f, pb = 0.0f;
        #pragma unroll
        for (int nt = 0; nt < 8; nt++) {
            sfr[nt][0] = fast_exp(sfr[nt][0] - mna);
            sfr[nt][1] = fast_exp(sfr[nt][1] - mna);
            sfr[nt][2] = fast_exp(sfr[nt][2] - mnb);
            sfr[nt][3] = fast_exp(sfr[nt][3] - mnb);
            pa += sfr[nt][0] + sfr[nt][1];
            pb += sfr[nt][2] + sfr[nt][3];
        }
        pa += __shfl_xor_sync(0xffffffffu, pa, 1);
        pa += __shfl_xor_sync(0xffffffffu, pa, 2);
        pb += __shfl_xor_sync(0xffffffffu, pb, 1);
        pb += __shfl_xor_sync(0xffffffffu, pb, 2);
        l0_ = l0_ * sc0 + pa; m0 = mna;
        l1_ = l1_ * sc1 + pb; m1 = mnb;
        #pragma unroll
        for (int nt = 0; nt < 8; nt++) {
            oacc[nt][0] *= sc0; oacc[nt][1] *= sc0;
            oacc[nt][2] *= sc1; oacc[nt][3] *= sc1;
        }

        if (!far) {
            #pragma unroll
            for (int nt = 0; nt < 8; nt++) {
                int sl0 = nt * 8 + cp * 2;
                pstg[lra * 66 + sl0]           = __float2bfloat16(sfr[nt][0]);
                pstg[lra * 66 + sl0 + 1]       = __float2bfloat16(sfr[nt][1]);
                pstg[(lra + 8) * 66 + sl0]     = __float2bfloat16(sfr[nt][2]);
                pstg[(lra + 8) * 66 + sl0 + 1] = __float2bfloat16(sfr[nt][3]);
            }
        }

        uint32_t ph[4][4], pl2[4][4];
        #pragma unroll
        for (int kk = 0; kk < 4; kk++) {
            packsplit(sfr[2*kk][0],   sfr[2*kk][1],   ph[kk][0], pl2[kk][0]);
            packsplit(sfr[2*kk][2],   sfr[2*kk][3],   ph[kk][1], pl2[kk][1]);
            packsplit(sfr[2*kk+1][0], sfr[2*kk+1][1], ph[kk][2], pl2[kk][2]);
            packsplit(sfr[2*kk+1][2], sfr[2*kk+1][3], ph[kk][3], pl2[kk][3]);
        }

        // ---- PV (vh/vl are [s][d] = [k][n] -> trans loads, unchanged) ----
        #pragma unroll
        for (int kk = 0; kk < 4; kk++) {
            const int k0 = kk * 16;
            #pragma unroll
            for (int ng = 0; ng < 4; ng++) {
                uint32_t bb[4];
                uint32_t sb = (uint32_t)__cvta_generic_to_shared(
                    &vh[(k0 + (lane & 15)) * 72 + ng * 16 + acol8]);
                LDSM_X4T(bb, sb);
                const int nt0 = ng * 2;
                MMA_BF16(oacc[nt0],     ph[kk][0], ph[kk][1], ph[kk][2], ph[kk][3], bb[0], bb[1]);
                MMA_BF16(oacc[nt0 + 1], ph[kk][0], ph[kk][1], ph[kk][2], ph[kk][3], bb[2], bb[3]);
                MMA_BF16(oacc[nt0],     pl2[kk][0], pl2[kk][1], pl2[kk][2], pl2[kk][3], bb[0], bb[1]);
                MMA_BF16(oacc[nt0 + 1], pl2[kk][0], pl2[kk][1], pl2[kk][2], pl2[kk][3], bb[2], bb[3]);
            }
        }
        #pragma unroll
        for (int kk = 0; kk < 4; kk++) {
            const int k0 = kk * 16;
            #pragma unroll
            for (int ng = 0; ng < 4; ng++) {
                uint32_t bb[4];
                uint32_t sb = (uint32_t)__cvta_generic_to_shared(
                    &vl[(k0 + (lane & 15)) * 72 + ng * 16 + acol8]);
                LDSM_X4T(bb, sb);
                const int nt0 = ng * 2;
                MMA_BF16(oacc[nt0],     ph[kk][0], ph[kk][1], ph[kk][2], ph[kk][3], bb[0], bb[1]);
                MMA_BF16(oacc[nt0 + 1], ph[kk][0], ph[kk][1], ph[kk][2], ph[kk][3], bb[2], bb[3]);
            }
        }

        if (!far) {
            __syncwarp();
            #pragma unroll
            for (int rsel = 0; rsel < 2; rsel++) {
                const int t = rsel ? tb2 : ta;
                const __nv_bfloat16* Prow = pstg + (size_t)(lra + rsel * 8) * 66;
                for (int j = 0; j <= 32; j++) {
                    int sl = t - 32 + j - s0c;
                    if (sl < 0 || sl > 63) continue;
                    float p = __bfloat162float(Prow[sl]);
                    #pragma unroll
                    for (int nt = 0; nt < 8; nt++) {
                        uint32_t rvu = *(const uint32_t*)&rvD[j * 72 + nt * 8 + cp * 2];
                        __nv_bfloat162 rv2 = *(__nv_bfloat162*)&rvu;
                        oacc[nt][rsel * 2 + 0] += p * __bfloat162float(rv2.x);
                        oacc[nt][rsel * 2 + 1] += p * __bfloat162float(rv2.y);
                    }
                }
            }
        }
    }

    const float invl0 = 1.0f / l0_, invl1 = 1.0f / l1_;
    #pragma unroll
    for (int rsel = 0; rsel < 2; rsel++) {
        const int t = rsel ? tb2 : ta;
        const float invl = rsel ? invl1 : invl0;
        #pragma unroll
        for (int nt = 0; nt < 8; nt++) {
            int c0 = nt * 8 + cp * 2;
            float o0 = oacc[nt][rsel * 2 + 0] * invl + rv0[c0];
            float o1 = oacc[nt][rsel * 2 + 1] * invl + rv0[c0 + 1];
            uint32_t hp, lp;
            packsplit(o0, o1, hp, lp);
            size_t oidx = (size_t)(b * T_ + t) * NX_ + h * 64 + c0;
            *(uint32_t*)&g_atts[0][oidx] = hp;
            *(uint32_t*)&g_atts[1][oidx] = lp;
        }
    }
}

// ---------------- launch ----------------
extern "C" void kernel_launch(void* const* d_in, const int* in_sizes, int n_in,
                              void* d_out, int out_size)
{
    const float* x          = (const float*)d_in[0];
    const int*   rel        = (const int*)  d_in[1];
    const float* tds        = (const float*)d_in[2];
    const float* LR_Q       = (const float*)d_in[3];
    const float* LR_K       = (const float*)d_in[4];
    const int*   LR_map     = (const int*)  d_in[5];
    const float* c_attn_w   = (const float*)d_in[6];
    const float* c_attn_b   = (const float*)d_in[7];
    const float* c_proj_w   = (const float*)d_in[8];
    const float* c_proj_b   = (const float*)d_in[9];
    const float* rel_w_emb  = (const float*)d_in[10];
    const float* rel_k_emb  = (const float*)d_in[11];
    const float* rel_v_emb  = (const float*)d_in[12];
    float* out = (float*)d_out;

    cudaFuncSetAttribute(attn_kernel, cudaFuncAttributeMaxDynamicSharedMemorySize,
                         ATT_SMEM);

    __nv_bfloat16 *xs, *w1s, *w2s, *atts;
    cudaGetSymbolAddress((void**)&xs, g_xs);
    cudaGetSymbolAddress((void**)&w1s, g_w1s);
    cudaGetSymbolAddress((void**)&w2s, g_w2s);
    cudaGetSymbolAddress((void**)&atts, g_atts);
    float* qkv_buf; cudaGetSymbolAddress((void**)&qkv_buf, g_qkv);

    const int NXM = B_ * T_ * NX_;
    split_kernel<<<NXM / 1024, 256>>>(x, xs, xs + NXM, NXM / 4);
    split_kernel<<<(NX_*3*NX_) / 1024, 256>>>(c_attn_w, w1s, w1s + NX_*3*NX_, (NX_*3*NX_) / 4);
    split_kernel<<<(NX_*NX_) / 1024, 256>>>(c_proj_w, w2s, w2s + NX_*NX_, (NX_*NX_) / 4);

    gemm_bf16x3s<<<dim3(24, 32), 256>>>(xs, w1s, c_attn_b, qkv_buf, 3072, 1);
    lr2_kernel<<<dim3(16, 64), 256>>>(LR_Q);
    attn_kernel<<<512, 256, ATT_SMEM>>>(
        rel, tds, LR_K, LR_map, rel_w_emb, rel_k_emb, rel_v_emb);
    gemm_bf16x3s<<<dim3(8, 32), 256>>>(atts, w2s, c_proj_b, out, 1024, 0);
}